// round 11
// baseline (speedup 1.0000x reference)
#include <cuda_runtime.h>
#include <cuda_bf16.h>

// Shapes: A=1, B=8, M=256, H(=Kdim)=2048, E=8, K=2, N=2048
// out (scalar) = sum_{b,e,k} sp[b,e] * hsum[b,k] * wsum[e,k]
// Fully fused single kernel:
//   bids 0..63     : hidden partial column sums (4 m-chunks) -> g_part, signal g_hdone
//   bids 64..2111  : W row sums (134 MB stream); at the end each warp waits for
//                    g_hdone, contracts its row-sum with c[e,k] computed from
//                    g_part + sp (one L2 load per lane), block-reduces in double,
//                    atomicAdd into 64 spread slots.
//   globally-last block (ticket) sums the slots, writes out, re-zeroes state
//   (state must be zero at kernel exit so CUDA-graph replays stay correct).

#define Bd 8
#define Md 256
#define Hd 2048
#define Ed 8
#define Nd 2048

#define MCHUNKS   4
#define H_BLOCKS  64                 // MCHUNKS * 16 k-blocks
#define W_BLOCKS  2048               // 8 warps/block, 1 warp per (e,k) row
#define NSLOTS    64

__device__ float        g_part[MCHUNKS * Bd * Hd];  // 256 KB  [c][b][k]
__device__ double       g_slots[NSLOTS];            // zero-init, re-zeroed at exit
__device__ unsigned int g_hdone;                    // hidden blocks done
__device__ unsigned int g_done;                     // ticket counter

__global__ void __launch_bounds__(256) k_fused(const float* __restrict__ W,
                                               const float* __restrict__ hidden,
                                               const float* __restrict__ sp,
                                               float* __restrict__ out) {
    __shared__ double s_red[8];
    const int tid  = threadIdx.x;
    const int warp = tid >> 5;
    const int lane = tid & 31;

    if (blockIdx.x < H_BLOCKS) {
        // ---------- hidden partial column sums ----------
        int idx = blockIdx.x;                 // 0..63
        int mc  = idx >> 4;                   // m chunk (0..3), 64 rows each
        int kb  = idx & 15;                   // k4 block (0..15)
        int g   = kb * 256 + tid;             // 0..4095 = b*512 + k4
        int b   = g >> 9;
        int k4  = g & 511;
        int m0  = mc * 64;

        const float4* src = reinterpret_cast<const float4*>(
            hidden + (size_t)(b * Md + m0) * Hd) + k4;

        float4 acc = make_float4(0.f, 0.f, 0.f, 0.f);
#pragma unroll 8
        for (int i = 0; i < 64; i++) {
            float4 v = src[i * (Hd / 4)];
            acc.x += v.x; acc.y += v.y; acc.z += v.z; acc.w += v.w;
        }
        reinterpret_cast<float4*>(g_part)[mc * 4096 + g] = acc;

        __syncthreads();
        if (tid == 0) {
            __threadfence();
            atomicAdd(&g_hdone, 1u);
        }
    } else {
        // ---------- W row sums + fused contraction ----------
        int row = (blockIdx.x - H_BLOCKS) * 8 + warp;   // e*2048 + k
        int e   = row >> 11;
        int k   = row & 2047;

        const float4* src = reinterpret_cast<const float4*>(W + (size_t)row * Nd);
        float s = 0.f;
#pragma unroll
        for (int i = 0; i < 16; i++) {                  // 16 f4 * 32 lanes = 2048
            float4 v = src[lane + 32 * i];
            s += (v.x + v.y) + (v.z + v.w);
        }
#pragma unroll
        for (int off = 16; off > 0; off >>= 1)
            s += __shfl_xor_sync(0xffffffff, s, off);   // all lanes hold s

        // wait for hidden partials (in practice already done ~18us earlier)
        if (lane == 0)
            while (*(volatile unsigned int*)&g_hdone < H_BLOCKS) { }
        __syncwarp();
        __threadfence();                                 // acquire

        // c[e,k] = sum_{c,b} part[c][b][k] * sp[b,e] ; one load per lane
        int c_ = lane >> 3;                              // 0..3
        int b_ = lane & 7;                               // 0..7
        float v = g_part[c_ * (Bd * Hd) + b_ * Hd + k] * sp[b_ * 16 + e];
#pragma unroll
        for (int off = 16; off > 0; off >>= 1)
            v += __shfl_xor_sync(0xffffffff, v, off);

        if (lane == 0) s_red[warp] = (double)s * (double)v;
        __syncthreads();
        if (warp == 0) {
            double d = (lane < 8) ? s_red[lane] : 0.0;
#pragma unroll
            for (int off = 4; off > 0; off >>= 1)
                d += __shfl_xor_sync(0xffffffff, d, off);
            if (lane == 0) atomicAdd(&g_slots[blockIdx.x & (NSLOTS - 1)], d);
        }
    }

    // ---------- common epilogue: ticket; last block finalizes ----------
    __syncthreads();
    if (tid == 0) {
        __threadfence();
        unsigned int ticket = atomicAdd(&g_done, 1u);
        if (ticket == gridDim.x - 1) {                   // all adds visible
            __threadfence();
            double total = 0.0;
#pragma unroll
            for (int i = 0; i < NSLOTS; i++) total += g_slots[i];
            out[0] = (float)total;
            // re-zero state for the next graph replay
#pragma unroll
            for (int i = 0; i < NSLOTS; i++) g_slots[i] = 0.0;
            g_hdone = 0u;
            __threadfence();
            g_done = 0u;
        }
    }
}

extern "C" void kernel_launch(void* const* d_in, const int* in_sizes, int n_in,
                              void* d_out, int out_size) {
    const float* hidden = (const float*)d_in[0];   // (1,8,256,2048)
    const float* sp     = (const float*)d_in[1];   // (1,8,2,8)
    const float* W      = (const float*)d_in[2];   // (1,8,2048,2048)
    float* out = (float*)d_out;

    k_fused<<<H_BLOCKS + W_BLOCKS, 256>>>(W, hidden, sp, out);
}

// round 12
// speedup vs baseline: 1.5618x; 1.5618x over previous
#include <cuda_runtime.h>
#include <cuda_bf16.h>

// Shapes: A=1, B=8, M=256, H(=Kdim)=2048, E=8, K=2, N=2048
// out (scalar) = sum_{b,e,k} sp[b,e] * hsum[b,k] * wsum[e,k]
//   hsum[b,k] = sum_m hidden[0,b,m,k]     (16 MB stream)
//   wsum[e,k] = sum_n W[0,e,k,n]          (134 MB stream)
//
// ONE kernel, NO mid-kernel waiting:
//   bids 0..2047    : W row sums (1 warp per (e,k) row) -> plain store g_wsum
//   bids 2048..2303 : hidden column sums (64 KB/block, uniform) -> RED.F32 g_hsum
//   every block     : bar.sync, thread0 atom.acq_rel ticket; last block's 256
//                     threads do the 128 KB L2 combine, write out, re-zero state.

#define Bd 8
#define Md 256
#define Hd 2048
#define Ed 8
#define Nd 2048

#define W_BLOCKS  2048
#define H_BLOCKS  256                // 16 m-chunks x 16 k-blocks, 64 KB each
#define GRID      (W_BLOCKS + H_BLOCKS)

__device__ float        g_wsum[Ed * Hd];   // plain stores, no init needed
__device__ float        g_hsum[Bd * Hd];   // MUST be zero at kernel entry (re-zeroed at exit)
__device__ unsigned int g_done;            // ticket (re-zeroed at exit)

__global__ void __launch_bounds__(256) k_all(const float* __restrict__ W,
                                             const float* __restrict__ hidden,
                                             const float* __restrict__ sp,
                                             float* __restrict__ out) {
    __shared__ unsigned int s_last;
    __shared__ float  s_sp[Bd * Ed];
    __shared__ double s_red[8];

    const int tid  = threadIdx.x;
    const int warp = tid >> 5;
    const int lane = tid & 31;

    if (blockIdx.x < W_BLOCKS) {
        // ---------- W row sums: one warp per row of 2048 floats ----------
        int row = blockIdx.x * 8 + warp;             // e*2048 + k
        const float4* src = reinterpret_cast<const float4*>(W + (size_t)row * Nd);
        float s = 0.f;
#pragma unroll
        for (int i = 0; i < 16; i++) {               // 16 f4 * 32 lanes = 2048
            float4 v = src[lane + 32 * i];
            s += (v.x + v.y) + (v.z + v.w);
        }
#pragma unroll
        for (int off = 16; off > 0; off >>= 1)
            s += __shfl_xor_sync(0xffffffff, s, off);
        if (lane == 0) g_wsum[row] = s;
    } else {
        // ---------- hidden column sums: 64 KB/block, spread float atomics ----------
        int idx = blockIdx.x - W_BLOCKS;             // 0..255
        int mc  = idx >> 4;                          // m chunk (0..15), 16 rows
        int kb  = idx & 15;                          // k4 block (0..15)
        int g   = kb * 256 + tid;                    // 0..4095 = b*512 + k4
        int b   = g >> 9;
        int k4  = g & 511;
        int m0  = mc * 16;

        const float4* src = reinterpret_cast<const float4*>(
            hidden + (size_t)(b * Md + m0) * Hd) + k4;

        float4 acc = make_float4(0.f, 0.f, 0.f, 0.f);
#pragma unroll
        for (int i = 0; i < 16; i++) {
            float4 v = src[i * (Hd / 4)];
            acc.x += v.x; acc.y += v.y; acc.z += v.z; acc.w += v.w;
        }
        float* dst = &g_hsum[b * Hd + k4 * 4];
        atomicAdd(dst + 0, acc.x);
        atomicAdd(dst + 1, acc.y);
        atomicAdd(dst + 2, acc.z);
        atomicAdd(dst + 3, acc.w);
    }

    // ---------- ticket epilogue (no fences in hot path) ----------
    __syncthreads();                                  // blockmates' writes hb thread0
    if (tid == 0) {
        unsigned int t;
        asm volatile("atom.acq_rel.gpu.add.u32 %0, [%1], %2;"
                     : "=r"(t) : "l"(&g_done), "r"(1u) : "memory");
        s_last = (t == GRID - 1) ? 1u : 0u;
    }
    __syncthreads();                                  // broadcast + extend acquire to block

    if (s_last) {
        // ---------- last block: combine 128 KB from L2 ----------
        if (tid < Bd * Ed)
            s_sp[tid] = __ldcg(&sp[(tid >> 3) * 16 + (tid & 7)]);  // sp(b, K=2, e), slice 0
        __syncthreads();

        double acc = 0.0;
#pragma unroll
        for (int kk = 0; kk < 8; kk++) {
            int k = kk * 256 + tid;                   // coalesced
            float ws[Ed];
#pragma unroll
            for (int e = 0; e < Ed; e++) ws[e] = __ldcg(&g_wsum[e * Hd + k]);
#pragma unroll
            for (int b = 0; b < Bd; b++) {
                float hs = __ldcg(&g_hsum[b * Hd + k]);
                float cb = 0.f;
#pragma unroll
                for (int e = 0; e < Ed; e++) cb += s_sp[b * Ed + e] * ws[e];
                acc += (double)(hs * cb);
                g_hsum[b * Hd + k] = 0.f;             // re-zero for next graph replay
            }
        }

        // double block-reduce
#pragma unroll
        for (int off = 16; off > 0; off >>= 1)
            acc += __shfl_xor_sync(0xffffffff, acc, off);
        if (lane == 0) s_red[warp] = acc;
        __syncthreads();
        if (warp == 0) {
            double d = (lane < 8) ? s_red[lane] : 0.0;
#pragma unroll
            for (int off = 4; off > 0; off >>= 1)
                d += __shfl_xor_sync(0xffffffff, d, off);
            if (lane == 0) {
                out[0] = (float)d;
                g_done = 0u;                          // reset ticket for next replay
            }
        }
    }
}

extern "C" void kernel_launch(void* const* d_in, const int* in_sizes, int n_in,
                              void* d_out, int out_size) {
    const float* hidden = (const float*)d_in[0];   // (1,8,256,2048)
    const float* sp     = (const float*)d_in[1];   // (1,8,2,8)
    const float* W      = (const float*)d_in[2];   // (1,8,2048,2048)
    float* out = (float*)d_out;

    k_all<<<GRID, 256>>>(W, hidden, sp, out);
}

// round 13
// speedup vs baseline: 1.5630x; 1.0007x over previous
#include <cuda_runtime.h>
#include <cuda_bf16.h>

// Shapes: A=1, B=8, M=256, H(=Kdim)=2048, E=8, K=2, N=2048
// out (scalar) = sum_{b,e,k} sp[b,e] * hsum[b,k] * wsum[e,k]
//   hsum[b,k] = sum_m hidden[0,b,m,k]     (16 MB stream)
//   wsum[e,k] = sum_n W[0,e,k,n]          (134 MB stream)
//
// ONE kernel, no mid-kernel waiting, and NO per-block acquire (no SM-wide
// L1-invalidate storms): blocks finish with a RELEASE-only ticket atomic;
// the single last block does ONE acq_rel fence, combines 128 KB from L2,
// writes out, and re-zeroes state for the next graph replay.

#define Bd 8
#define Md 256
#define Hd 2048
#define Ed 8
#define Nd 2048

#define W_BLOCKS  2048
#define H_BLOCKS  256                // 16 m-chunks x 16 k-blocks, 64 KB each
#define GRID      (W_BLOCKS + H_BLOCKS)

__device__ float        g_wsum[Ed * Hd];   // plain stores
__device__ float        g_hsum[Bd * Hd];   // zero at entry (re-zeroed at exit)
__device__ unsigned int g_done;            // ticket (re-zeroed at exit)

__global__ void __launch_bounds__(256) k_all(const float* __restrict__ W,
                                             const float* __restrict__ hidden,
                                             const float* __restrict__ sp,
                                             float* __restrict__ out) {
    __shared__ unsigned int s_last;
    __shared__ float  s_sp[Bd * Ed];
    __shared__ double s_red[8];

    const int tid  = threadIdx.x;
    const int warp = tid >> 5;
    const int lane = tid & 31;

    if (blockIdx.x < W_BLOCKS) {
        // ---------- W row sums: one warp per row of 2048 floats ----------
        int row = blockIdx.x * 8 + warp;             // e*2048 + k
        const float4* src = reinterpret_cast<const float4*>(W + (size_t)row * Nd);
        float s = 0.f;
#pragma unroll
        for (int i = 0; i < 16; i++) {               // 16 f4 * 32 lanes = 2048
            float4 v = src[lane + 32 * i];
            s += (v.x + v.y) + (v.z + v.w);
        }
#pragma unroll
        for (int off = 16; off > 0; off >>= 1)
            s += __shfl_xor_sync(0xffffffff, s, off);
        if (lane == 0) g_wsum[row] = s;
    } else {
        // ---------- hidden column sums: 64 KB/block, spread relaxed atomics ----------
        int idx = blockIdx.x - W_BLOCKS;             // 0..255
        int mc  = idx >> 4;                          // m chunk (0..15), 16 rows
        int kb  = idx & 15;                          // k4 block (0..15)
        int g   = kb * 256 + tid;                    // 0..4095 = b*512 + k4
        int b   = g >> 9;
        int k4  = g & 511;
        int m0  = mc * 16;

        const float4* src = reinterpret_cast<const float4*>(
            hidden + (size_t)(b * Md + m0) * Hd) + k4;

        float4 acc = make_float4(0.f, 0.f, 0.f, 0.f);
#pragma unroll
        for (int i = 0; i < 16; i++) {
            float4 v = src[i * (Hd / 4)];
            acc.x += v.x; acc.y += v.y; acc.z += v.z; acc.w += v.w;
        }
        float* dst = &g_hsum[b * Hd + k4 * 4];
        atomicAdd(dst + 0, acc.x);                   // relaxed RED, no fences
        atomicAdd(dst + 1, acc.y);
        atomicAdd(dst + 2, acc.z);
        atomicAdd(dst + 3, acc.w);
    }

    // ---------- ticket epilogue: RELEASE-only (no L1 invalidate) ----------
    __syncthreads();
    if (tid == 0) {
        unsigned int t;
        asm volatile("atom.release.gpu.global.add.u32 %0, [%1], %2;"
                     : "=r"(t) : "l"(&g_done), "r"(1u) : "memory");
        if (t == GRID - 1) {
            // single acquire on a drained chip: one-time cost
            asm volatile("fence.acq_rel.gpu;" ::: "memory");
            s_last = 1u;
        } else {
            s_last = 0u;
        }
    }
    __syncthreads();

    if (s_last) {
        // ---------- last block: combine 128 KB from L2 ----------
        if (tid < Bd * Ed)
            s_sp[tid] = __ldcg(&sp[(tid >> 3) * 16 + (tid & 7)]);  // sp(b, K=2, e), slice 0
        __syncthreads();

        double acc = 0.0;
#pragma unroll
        for (int kk = 0; kk < 8; kk++) {
            int k = kk * 256 + tid;                   // coalesced
            float ws[Ed];
#pragma unroll
            for (int e = 0; e < Ed; e++) ws[e] = __ldcg(&g_wsum[e * Hd + k]);
#pragma unroll
            for (int b = 0; b < Bd; b++) {
                float hs = __ldcg(&g_hsum[b * Hd + k]);
                float cb = 0.f;
#pragma unroll
                for (int e = 0; e < Ed; e++) cb += s_sp[b * Ed + e] * ws[e];
                acc += (double)(hs * cb);
                g_hsum[b * Hd + k] = 0.f;             // re-zero for next graph replay
            }
        }

        // double block-reduce
#pragma unroll
        for (int off = 16; off > 0; off >>= 1)
            acc += __shfl_xor_sync(0xffffffff, acc, off);
        if (lane == 0) s_red[warp] = acc;
        __syncthreads();
        if (warp == 0) {
            double d = (lane < 8) ? s_red[lane] : 0.0;
#pragma unroll
            for (int off = 4; off > 0; off >>= 1)
                d += __shfl_xor_sync(0xffffffff, d, off);
            if (lane == 0) {
                out[0] = (float)d;
                g_done = 0u;                          // reset ticket for next replay
            }
        }
    }
}

extern "C" void kernel_launch(void* const* d_in, const int* in_sizes, int n_in,
                              void* d_out, int out_size) {
    const float* hidden = (const float*)d_in[0];   // (1,8,256,2048)
    const float* sp     = (const float*)d_in[1];   // (1,8,2,8)
    const float* W      = (const float*)d_in[2];   // (1,8,2048,2048)
    float* out = (float*)d_out;

    k_all<<<GRID, 256>>>(W, hidden, sp, out);
}

// round 14
// speedup vs baseline: 2.1875x; 1.3996x over previous
#include <cuda_runtime.h>
#include <cuda_bf16.h>

// Shapes: A=1, B=8, M=256, H(=Kdim)=2048, E=8, K=2, N=2048
// out (scalar) = sum_{b,e,k} sp[b,e] * hsum[b,k] * wsum[e,k]
//   hsum[b,k] = sum_m hidden[0,b,m,k]     (16 MB stream)
//   wsum[e,k] = sum_n W[0,e,k,n]          (134 MB stream)
//
// R9's proven two-kernel structure (stream at HBM ceiling + tiny combine),
// with the combine launched via PDL (programmatic dependent launch) so its
// ~5us launch overhead overlaps the stream kernel. griddepcontrol.wait
// guarantees visibility of the primary's plain stores -> no atomics/fences
// in the streaming path at all.

#define Bd 8
#define Md 256
#define Hd 2048
#define Ed 8
#define Nd 2048

#define W_BLOCKS   2048            // 8 warps/block, 1 warp per (e,k) row
#define H_BLOCKS   256             // 16 m-chunks x 16 k-blocks
#define MCHUNKS    16

__device__ float  g_wsum[Ed * Hd];            // 64 KB
__device__ float  g_part[MCHUNKS * Bd * Hd];  // 1 MB partial hidden sums
__device__ double g_acc;
__device__ unsigned int g_done;

// ---------------- kernel 1: all 150 MB of streaming, one wave-set ----------------
__global__ void __launch_bounds__(256) k_stream(const float* __restrict__ W,
                                                const float* __restrict__ hidden) {
    if (blockIdx.x == 0 && threadIdx.x == 0) { g_acc = 0.0; g_done = 0u; }

    if (blockIdx.x < W_BLOCKS) {
        // ---- W row sums: one warp per row of 2048 floats ----
        int warp = threadIdx.x >> 5;
        int lane = threadIdx.x & 31;
        int row  = blockIdx.x * 8 + warp;            // e*2048 + k

        const float4* src = reinterpret_cast<const float4*>(W + (size_t)row * Nd);
        float s = 0.f;
#pragma unroll
        for (int i = 0; i < 16; i++) {               // 16 f4 * 32 lanes = 2048 floats
            float4 v = src[lane + 32 * i];
            s += (v.x + v.y) + (v.z + v.w);
        }
#pragma unroll
        for (int off = 16; off > 0; off >>= 1)
            s += __shfl_xor_sync(0xffffffff, s, off);
        if (lane == 0) g_wsum[row] = s;
    } else {
        // ---- hidden partial column sums: 64 KB per block, plain stores ----
        int idx = blockIdx.x - W_BLOCKS;             // 0..255
        int mc  = idx >> 4;                          // m chunk (0..15)
        int kb  = idx & 15;                          // k4 block (0..15)
        int g   = kb * 256 + threadIdx.x;            // 0..4095 = b*512 + k4
        int b   = g >> 9;
        int k4  = g & 511;
        int m0  = mc * 16;

        const float4* src = reinterpret_cast<const float4*>(
            hidden + (size_t)(b * Md + m0) * Hd) + k4;

        float4 acc = make_float4(0.f, 0.f, 0.f, 0.f);
#pragma unroll
        for (int i = 0; i < 16; i++) {
            float4 v = src[i * (Hd / 4)];
            acc.x += v.x; acc.y += v.y; acc.z += v.z; acc.w += v.w;
        }
        reinterpret_cast<float4*>(g_part)[mc * 4096 + g] = acc;   // [c][b][k] layout
    }

    // Signal dependent grid: all prior stores become visible to the secondary
    // after its griddepcontrol.wait.
    asm volatile("griddepcontrol.launch_dependents;");
}

// ---------------- kernel 2: parallel contraction + output (PDL secondary) ----------------
// 64 blocks x 256 = 16384 threads; thread t owns (b = t>>11, k = t&2047).
__global__ void __launch_bounds__(256) k_combine(const float* __restrict__ sp,
                                                 float* __restrict__ out) {
    int t = blockIdx.x * 256 + threadIdx.x;          // 0..16383
    int b = t >> 11;                                 // 0..7
    int k = t & 2047;                                // 0..2047

    // Prologue (independent of primary): load sp coefficients into registers.
    float spc[Ed];
#pragma unroll
    for (int e = 0; e < Ed; e++)
        spc[e] = sp[b * 16 + e];                     // sp layout (b, K=2, e): k-slice 0

    // Block until the primary grid's memory is visible (no-op if launched
    // without PDL -> safe fallback path).
    asm volatile("griddepcontrol.wait;");

    // hsum[b,k] = sum over 16 m-chunk partials (independent loads -> MLP=16)
    float hs = 0.f;
#pragma unroll
    for (int c = 0; c < MCHUNKS; c++)
        hs += g_part[c * (Bd * Hd) + b * Hd + k];

    // cb = sum_e sp[b,e] * wsum[e,k]
    float cb = 0.f;
#pragma unroll
    for (int e = 0; e < Ed; e++)
        cb += spc[e] * g_wsum[e * Hd + k];

    double acc = (double)hs * (double)cb;

    // warp reduce (double), one atomic per warp
#pragma unroll
    for (int off = 16; off > 0; off >>= 1)
        acc += __shfl_xor_sync(0xffffffff, acc, off);
    if ((threadIdx.x & 31) == 0) atomicAdd(&g_acc, acc);

    // last-block-done writes the scalar output
    __syncthreads();
    if (threadIdx.x == 0) {
        __threadfence();
        unsigned int ticket = atomicAdd(&g_done, 1u);
        if (ticket == gridDim.x - 1) {
            __threadfence();
            out[0] = (float)g_acc;
        }
    }
}

extern "C" void kernel_launch(void* const* d_in, const int* in_sizes, int n_in,
                              void* d_out, int out_size) {
    const float* hidden = (const float*)d_in[0];   // (1,8,256,2048)
    const float* sp     = (const float*)d_in[1];   // (1,8,2,8)
    const float* W      = (const float*)d_in[2];   // (1,8,2048,2048)
    float* out = (float*)d_out;

    k_stream<<<W_BLOCKS + H_BLOCKS, 256>>>(W, hidden);

    // Secondary with Programmatic Dependent Launch: begins launching while
    // k_stream still runs, blocks at griddepcontrol.wait.
    cudaLaunchConfig_t cfg = {};
    cfg.gridDim  = dim3(64, 1, 1);
    cfg.blockDim = dim3(256, 1, 1);
    cfg.dynamicSmemBytes = 0;
    cfg.stream = (cudaStream_t)0;                  // same (captured) stream as <<<>>>
    cudaLaunchAttribute attr[1];
    attr[0].id = cudaLaunchAttributeProgrammaticStreamSerialization;
    attr[0].val.programmaticStreamSerializationAllowed = 1;
    cfg.attrs = attr;
    cfg.numAttrs = 1;

    cudaError_t err = cudaLaunchKernelEx(&cfg, k_combine, sp, out);
    if (err != cudaSuccess) {
        // Fallback: plain serialized launch (griddepcontrol.wait is a no-op).
        k_combine<<<64, 256>>>(sp, out);
    }
}